// round 2
// baseline (speedup 1.0000x reference)
#include <cuda_runtime.h>
#include <cstdint>

#define ROWS   65536
#define NE     1024
#define ED     64
#define CHUNK  128
#define NCHUNK (NE / CHUNK)   // 8
#define TPB    256
#define WROW   (CHUNK + 2)    // 130 ull per dp-row: 1040B stride (16B aligned)

// Output layout (tuple flattened, all float32) — validated in R1
#define OFF_LOSS  0
#define OFF_L1    1
#define OFF_L2    2
#define OFF_ZQST  3
#define OFF_ZOUT  4194307
#define OFF_PERP  8388611
#define OFF_OH    8388612
#define OFF_IDX   75497476

__device__ int    g_hist[NE];
__device__ double g_loss;
__device__ float  g_wsum[NE];

__device__ __forceinline__ void ffma2(unsigned long long &acc,
                                      unsigned long long a,
                                      unsigned long long b) {
    asm("fma.rn.f32x2 %0, %1, %2, %0;" : "+l"(acc) : "l"(a), "l"(b));
}
__device__ __forceinline__ unsigned long long pack2(float x, float y) {
    unsigned long long r;
    asm("mov.b64 %0, {%1, %2};" : "=l"(r) : "f"(x), "f"(y));
    return r;
}
__device__ __forceinline__ float2 unpack2(unsigned long long v) {
    float2 r;
    asm("mov.b64 {%0, %1}, %2;" : "=f"(r.x), "=f"(r.y) : "l"(v));
    return r;
}

// ---------------------------------------------------------------------------
// prep: per-entry ||w||^2, zero histogram + loss accumulator
// ---------------------------------------------------------------------------
__global__ void vq_prep(const float* __restrict__ w) {
    int e = blockIdx.x, lane = threadIdx.x;
    const float* wr = w + e * ED;
    float a = wr[lane], b = wr[lane + 32];
    float s = a * a + b * b;
    #pragma unroll
    for (int o = 16; o; o >>= 1) s += __shfl_down_sync(0xffffffffu, s, o);
    if (lane == 0) {
        g_wsum[e] = s;
        g_hist[e] = 0;
        if (e == 0) g_loss = 0.0;
    }
}

// ---------------------------------------------------------------------------
// main: one row per lane in registers. w chunk staged to smem transposed
// [dp][entry] so one LDS.128 broadcast feeds 2 FFMA2. One-hot zero slices
// written fire-and-forget inside the chunk loop (overlaps compute); the
// single 1.0 + z_q epilogue written after the argmin.
// ---------------------------------------------------------------------------
__global__ __launch_bounds__(TPB, 2) void vq_main(
    const float* __restrict__ z, const float* __restrict__ w,
    float* __restrict__ out)
{
    __shared__ __align__(16) unsigned long long ws[32][WROW];  // 33280 B
    __shared__ float  wsm[CHUNK];
    __shared__ double lred[TPB / 32];

    const int tid  = threadIdx.x;
    const int lane = tid & 31, warp = tid >> 5;
    const int grow = blockIdx.x * TPB + tid;   // this lane's row

    // ---- load my row into registers (64 fp32 as 32 f32x2 pairs) ----
    unsigned long long zreg[32];
    float zsum = 0.f;
    {
        const float4* zp = (const float4*)(z + (size_t)grow * ED);
        #pragma unroll
        for (int j = 0; j < 16; j++) {
            float4 v = zp[j];
            zreg[2 * j]     = pack2(v.x, v.y);
            zreg[2 * j + 1] = pack2(v.z, v.w);
            // ascending scalar order, same expression form as R1 (bit-match)
            zsum += v.x * v.x; zsum += v.y * v.y;
            zsum += v.z * v.z; zsum += v.w * v.w;
        }
    }

    float best = 3.402823e38f;
    int   bidx = 0;

    float4* ohp = (float4*)(out + OFF_OH + (size_t)grow * NE);
    const float4 zero4 = make_float4(0.f, 0.f, 0.f, 0.f);

    for (int c = 0; c < NCHUNK; c++) {
        __syncthreads();   // protect ws reuse
        // stage w chunk transposed: ws[dp][e] = f32x2 of dims (2dp, 2dp+1)
        {
            const float4* wg = (const float4*)w + (size_t)c * CHUNK * 16;
            #pragma unroll
            for (int i = tid; i < CHUNK * 16; i += TPB) {
                int e = i >> 4, dpp = i & 15;
                float4 v = wg[i];
                ws[2 * dpp][e]     = pack2(v.x, v.y);
                ws[2 * dpp + 1][e] = pack2(v.z, v.w);
            }
            if (tid < CHUNK) wsm[tid] = g_wsum[c * CHUNK + tid];
        }
        __syncthreads();

        // fire-and-forget: zero this chunk's slice of my one-hot row
        #pragma unroll
        for (int j = 0; j < CHUNK / 4; j++) ohp[c * (CHUNK / 4) + j] = zero4;

        for (int e = 0; e < CHUNK; e += 2) {
            unsigned long long a0 = 0ull, a1 = 0ull;
            #pragma unroll
            for (int dp = 0; dp < 32; dp++) {
                ulonglong2 wv = *(const ulonglong2*)&ws[dp][e];
                ffma2(a0, zreg[dp], wv.x);
                ffma2(a1, zreg[dp], wv.y);
            }
            float2 d0 = unpack2(a0), d1 = unpack2(a1);
            float dot0 = d0.x + d0.y;
            float dot1 = d1.x + d1.y;
            int   e0 = c * CHUNK + e;
            float t0 = zsum + wsm[e];
            float s0 = t0 - 2.0f * dot0;       // same form as R1
            float t1 = zsum + wsm[e + 1];
            float s1 = t1 - 2.0f * dot1;
            if (s0 < best) { best = s0; bidx = e0; }
            if (s1 < best) { best = s1; bidx = e0 + 1; }
        }
    }

    // ---- epilogue: this lane fully owns its row ----
    const int id = bidx;
    atomicAdd(&g_hist[id], 1);
    out[OFF_IDX + grow] = (float)id;

    const float* wrow = w + (size_t)id * ED;
    float dsq = 0.f;
    #pragma unroll
    for (int j = 0; j < 32; j++) {
        float2 zr = unpack2(zreg[j]);
        float q0 = wrow[2 * j], q1 = wrow[2 * j + 1];
        float df0 = q0 - zr.x, df1 = q1 - zr.y;
        float st0 = zr.x + df0, st1 = zr.y + df1;  // straight-through replay
        size_t o = (size_t)grow * ED + 2 * j;
        out[OFF_ZQST + o]     = st0;
        out[OFF_ZQST + o + 1] = st1;
        out[OFF_ZOUT + o]     = st0;
        out[OFF_ZOUT + o + 1] = st1;
        dsq += df0 * df0; dsq += df1 * df1;
    }
    // one-hot 1.0 (ordered after this thread's zero of the same address)
    out[OFF_OH + (size_t)grow * NE + id] = 1.0f;

    // block-level loss reduction -> one atomic per block
    #pragma unroll
    for (int o = 16; o; o >>= 1) dsq += __shfl_down_sync(0xffffffffu, dsq, o);
    if (lane == 0) lred[warp] = (double)dsq;
    __syncthreads();
    if (tid == 0) {
        double s = 0.0;
        #pragma unroll
        for (int i = 0; i < TPB / 32; i++) s += lred[i];
        atomicAdd(&g_loss, s);
    }
}

// ---------------------------------------------------------------------------
// finalize: losses + perplexity scalars
// ---------------------------------------------------------------------------
__global__ void vq_finalize(float* __restrict__ out) {
    __shared__ float red[1024];
    int t = threadIdx.x;
    float p = (float)g_hist[t] / 65536.0f;
    red[t] = p * logf(p + 1e-10f);
    __syncthreads();
    #pragma unroll
    for (int s = 512; s; s >>= 1) {
        if (t < s) red[t] += red[t + s];
        __syncthreads();
    }
    if (t == 0) {
        out[OFF_PERP] = expf(-red[0]);
        float l1 = (float)(g_loss / 4194304.0);
        out[OFF_L1] = l1;
        out[OFF_L2] = l1;
        out[OFF_LOSS] = l1 + 0.25f * l1;
    }
}

// ---------------------------------------------------------------------------
extern "C" void kernel_launch(void* const* d_in, const int* in_sizes, int n_in,
                              void* d_out, int out_size)
{
    const float* z = (const float*)d_in[0];   // (8192, 512)
    const float* w = (const float*)d_in[1];   // (1024, 64)
    float* out = (float*)d_out;

    vq_prep<<<NE, 32>>>(w);
    vq_main<<<ROWS / TPB, TPB>>>(z, w, out);
    vq_finalize<<<1, 1024>>>(out);
}

// round 4
// speedup vs baseline: 1.7232x; 1.7232x over previous
#include <cuda_runtime.h>
#include <cstdint>

// Problem constants
#define ROWS   65536        // B*n = 8192*8
#define NE     1024         // codebook size
#define ED     64           // codebook dim
#define CHUNK  128          // codebook entries staged per iteration
#define NCHUNK (NE / CHUNK) // 8
#define RPB    64           // rows per block
#define TR     8            // rows per warp (8 warps * 8 = 64)
#define TE     4            // entries per lane per chunk (CHUNK/32)

// Output layout (tuple flattened, all float32) — validated R1/R2
#define OFF_LOSS  0
#define OFF_L1    1
#define OFF_L2    2
#define OFF_ZQST  3
#define OFF_ZOUT  4194307
#define OFF_PERP  8388611
#define OFF_OH    8388612
#define OFF_IDX   75497476

__device__ int    g_hist[NE];
__device__ double g_loss;
__device__ float  g_wsum[NE];

__device__ __forceinline__ void ffma2(unsigned long long &acc,
                                      unsigned long long a,
                                      unsigned long long b) {
    asm("fma.rn.f32x2 %0, %1, %2, %0;" : "+l"(acc) : "l"(a), "l"(b));
}
__device__ __forceinline__ float2 unpack2(unsigned long long v) {
    float2 r;
    asm("mov.b64 {%0, %1}, %2;" : "=f"(r.x), "=f"(r.y) : "l"(v));
    return r;
}

// ---------------------------------------------------------------------------
// prep: per-entry ||w||^2, zero histogram + loss accumulator
// ---------------------------------------------------------------------------
__global__ void vq_prep(const float* __restrict__ w) {
    int e = blockIdx.x, lane = threadIdx.x;
    const float* wr = w + e * ED;
    float a = wr[lane], b = wr[lane + 32];
    float s = a * a + b * b;
    #pragma unroll
    for (int o = 16; o; o >>= 1) s += __shfl_down_sync(0xffffffffu, s, o);
    if (lane == 0) {
        g_wsum[e] = s;
        g_hist[e] = 0;
        if (e == 0) g_loss = 0.0;
    }
}

// ---------------------------------------------------------------------------
// main kernel: fused distance-GEMM + row argmin + one-hot + z_q epilogue.
// Block: 64 rows. Warp: 8 rows (broadcast from smem). Lane: 4 entries/chunk.
// zsum lives in registers (lane r<8 owns row myRow0+r, sequential d-order),
// fetched by shuffle -> smem is exactly 49152 B (the 0xc000 static limit).
// One-hot zeros written fire-and-forget inside the chunk loop; the 1.0 is
// ordered after them by the post-loop __syncthreads (block fence).
// Scores computed exactly as R1: (||z||^2 + ||w||^2) - 2*dot, fp32.
// ---------------------------------------------------------------------------
__global__ __launch_bounds__(256) void vq_argmin(
    const float* __restrict__ z, const float* __restrict__ w,
    float* __restrict__ out)
{
    __shared__ float  zs[RPB * ED];       // 16384 B: z tile (row-major)
    __shared__ float2 wp[32 * CHUNK];     // 32768 B: w chunk [dpair][entry] swizzled

    const int tid = threadIdx.x, lane = tid & 31, warp = tid >> 5;
    const int rowBase = blockIdx.x * RPB;
    const int myRow0 = warp * TR;

    // stage z tile (coalesced float4)
    {
        const float4* zg = (const float4*)(z + (size_t)rowBase * ED);
        float4* zt = (float4*)zs;
        #pragma unroll
        for (int i = tid; i < RPB * ED / 4; i += 256) zt[i] = zg[i];
    }
    __syncthreads();

    // per-warp zsum: lane r (<8) owns row myRow0+r, sequential order (= R1)
    float myzsum = 0.f;
    if (lane < TR) {
        const float* zr = zs + (myRow0 + lane) * ED;
        #pragma unroll
        for (int d = 0; d < ED; d++) myzsum += zr[d] * zr[d];
    }

    float best[TR]; int bidx[TR];
    #pragma unroll
    for (int r = 0; r < TR; r++) { best[r] = 3.402823e38f; bidx[r] = 0x7fffffff; }

    const float2* zs2 = (const float2*)zs;
    float4* ohp = (float4*)(out + OFF_OH + (size_t)rowBase * NE);
    const float4 zero4 = make_float4(0.f, 0.f, 0.f, 0.f);

    for (int c = 0; c < NE; c += CHUNK) {
        __syncthreads();   // protect wp reuse
        // stage w chunk as [dpair][entry] with xor-swizzle (conflict-free LDS)
        {
            const float2* wg = (const float2*)(w + (size_t)c * ED);
            #pragma unroll
            for (int i = tid; i < CHUNK * 32; i += 256) {
                int e = i >> 5, dp = i & 31;
                int col = (e & ~31) | ((e & 31) ^ dp);
                wp[dp * CHUNK + col] = wg[i];
            }
        }
        __syncthreads();

        // fire-and-forget: zero 1/NCHUNK of this block's one-hot slice
        {
            int it = c / CHUNK;                    // 0..7
            #pragma unroll
            for (int k = 0; k < (RPB * NE / 4) / (NCHUNK * 256); k++)
                ohp[it * (RPB * NE / 4 / NCHUNK) + k * 256 + tid] = zero4;
        }

        unsigned long long acc[TR][TE];
        #pragma unroll
        for (int r = 0; r < TR; r++)
            #pragma unroll
            for (int j = 0; j < TE; j++) acc[r][j] = 0ull;

        #pragma unroll 8
        for (int dp = 0; dp < 32; dp++) {
            unsigned long long zv[TR], wv[TE];
            #pragma unroll
            for (int r = 0; r < TR; r++)
                zv[r] = *(const unsigned long long*)&zs2[(myRow0 + r) * 32 + dp];
            #pragma unroll
            for (int j = 0; j < TE; j++) {
                int col = (j << 5) | (lane ^ dp);
                wv[j] = *(const unsigned long long*)&wp[dp * CHUNK + col];
            }
            #pragma unroll
            for (int r = 0; r < TR; r++)
                #pragma unroll
                for (int j = 0; j < TE; j++)
                    ffma2(acc[r][j], zv[r], wv[j]);
        }

        #pragma unroll
        for (int r = 0; r < TR; r++) {
            float zsr = __shfl_sync(0xffffffffu, myzsum, r);
            #pragma unroll
            for (int j = 0; j < TE; j++) {
                float2 a = unpack2(acc[r][j]);
                float dot = a.x + a.y;
                int e = c + (j << 5) + lane;
                float t = zsr + g_wsum[e];
                float s = t - 2.0f * dot;      // matches reference fp32 ordering
                if (s < best[r] || (s == best[r] && e < bidx[r])) {
                    best[r] = s; bidx[r] = e;
                }
            }
        }
    }

    __syncthreads();   // fence: all one-hot zeros precede the 1.0 stores below

    // per-row warp reduction + epilogue
    double dacc = 0.0;
    #pragma unroll
    for (int r = 0; r < TR; r++) {
        float v = best[r]; int id = bidx[r];
        #pragma unroll
        for (int o = 16; o; o >>= 1) {
            float v2 = __shfl_down_sync(0xffffffffu, v, o);
            int   i2 = __shfl_down_sync(0xffffffffu, id, o);
            if (v2 < v || (v2 == v && i2 < id)) { v = v2; id = i2; }
        }
        id = __shfl_sync(0xffffffffu, id, 0);

        int grow = rowBase + myRow0 + r;
        const float* wrow = w + (size_t)id * ED;
        float dsq = 0.f;
        #pragma unroll
        for (int d = lane; d < ED; d += 32) {
            float zq = wrow[d];                  // z_q = exact codebook row
            float zr = zs[(myRow0 + r) * ED + d];
            float df = zq - zr;
            float st = zr + df;                  // straight-through fp32 replay
            out[OFF_ZQST + (size_t)grow * ED + d] = st;
            out[OFF_ZOUT + (size_t)grow * ED + d] = st;
            dsq += df * df;
        }
        #pragma unroll
        for (int o = 16; o; o >>= 1) dsq += __shfl_down_sync(0xffffffffu, dsq, o);
        if (lane == 0) {
            atomicAdd(&g_hist[id], 1);
            out[OFF_IDX + grow] = (float)id;
            out[OFF_OH + (size_t)grow * NE + id] = 1.0f;   // after fenced zeros
            dacc += (double)dsq;
        }
    }
    if (lane == 0 && dacc != 0.0) atomicAdd(&g_loss, dacc);
}

// ---------------------------------------------------------------------------
// finalize: losses + perplexity scalars
// ---------------------------------------------------------------------------
__global__ void vq_finalize(float* __restrict__ out) {
    __shared__ float red[1024];
    int t = threadIdx.x;
    float p = (float)g_hist[t] / 65536.0f;
    red[t] = p * logf(p + 1e-10f);
    __syncthreads();
    #pragma unroll
    for (int s = 512; s; s >>= 1) {
        if (t < s) red[t] += red[t + s];
        __syncthreads();
    }
    if (t == 0) {
        out[OFF_PERP] = expf(-red[0]);
        float l1 = (float)(g_loss / 4194304.0);
        out[OFF_L1] = l1;
        out[OFF_L2] = l1;                 // loss2 == loss1 numerically
        out[OFF_LOSS] = l1 + 0.25f * l1;  // GAMMA*l1 + BETA*l2
    }
}

// ---------------------------------------------------------------------------
extern "C" void kernel_launch(void* const* d_in, const int* in_sizes, int n_in,
                              void* d_out, int out_size)
{
    const float* z = (const float*)d_in[0];   // (8192, 512)
    const float* w = (const float*)d_in[1];   // (1024, 64)
    float* out = (float*)d_out;

    vq_prep<<<NE, 32>>>(w);
    vq_argmin<<<ROWS / RPB, 256>>>(z, w, out);
    vq_finalize<<<1, 1024>>>(out);
}